// round 1
// baseline (speedup 1.0000x reference)
#include <cuda_runtime.h>

// Problem constants (fixed by the reference):
//   hidden [B, L, D] fp32, ids [B, L] int32, mask [B, L] int32, idf [V] fp32
//   out[b, d] = sum_l hidden[b,l,d] * (mask[b,l] ? idf[ids[b,l]] : 0) / max(sum_l mask[b,l], 1e-9)
#define B_SZ 4096
#define L_SZ 100
#define D_SZ 768
#define THREADS 192   // D/4 float4 lanes

__global__ __launch_bounds__(THREADS, 8)
void sbert_idf_pool_kernel(const float* __restrict__ hidden,
                           const int*   __restrict__ ids,
                           const int*   __restrict__ mask,
                           const float* __restrict__ idf,
                           float*       __restrict__ out) {
    __shared__ float wm[L_SZ];

    const int b   = blockIdx.x;
    const int tid = threadIdx.x;

    // ---- prologue: per-token weight gather + mask count -------------------
    int m = 0;
    if (tid < L_SZ) {
        m = mask[b * L_SZ + tid];
        float w = 0.0f;
        if (m != 0) {
            w = __ldg(&idf[ids[b * L_SZ + tid]]);
        }
        wm[tid] = w;
    }
    // barrier + popcount of mask across the block in one instruction
    int nmask = __syncthreads_count(m != 0);
    float inv = 1.0f / fmaxf((float)nmask, 1e-9f);

    // ---- mainloop: stream 100 x 3072B rows, coalesced float4 --------------
    const float4* __restrict__ h =
        reinterpret_cast<const float4*>(hidden + (long long)b * (L_SZ * D_SZ)) + tid;

    float4 a0 = make_float4(0.f, 0.f, 0.f, 0.f);
    float4 a1 = a0, a2 = a0, a3 = a0;

    #pragma unroll
    for (int l = 0; l < L_SZ; l += 4) {
        const float w0 = wm[l + 0];
        const float w1 = wm[l + 1];
        const float w2 = wm[l + 2];
        const float w3 = wm[l + 3];
        // 4 independent loads -> 4 in-flight LDG.128 per body (MLP)
        const float4 h0 = h[(l + 0) * (D_SZ / 4)];
        const float4 h1 = h[(l + 1) * (D_SZ / 4)];
        const float4 h2 = h[(l + 2) * (D_SZ / 4)];
        const float4 h3 = h[(l + 3) * (D_SZ / 4)];
        a0.x = fmaf(h0.x, w0, a0.x); a0.y = fmaf(h0.y, w0, a0.y);
        a0.z = fmaf(h0.z, w0, a0.z); a0.w = fmaf(h0.w, w0, a0.w);
        a1.x = fmaf(h1.x, w1, a1.x); a1.y = fmaf(h1.y, w1, a1.y);
        a1.z = fmaf(h1.z, w1, a1.z); a1.w = fmaf(h1.w, w1, a1.w);
        a2.x = fmaf(h2.x, w2, a2.x); a2.y = fmaf(h2.y, w2, a2.y);
        a2.z = fmaf(h2.z, w2, a2.z); a2.w = fmaf(h2.w, w2, a2.w);
        a3.x = fmaf(h3.x, w3, a3.x); a3.y = fmaf(h3.y, w3, a3.y);
        a3.z = fmaf(h3.z, w3, a3.z); a3.w = fmaf(h3.w, w3, a3.w);
    }

    float4 r;
    r.x = (a0.x + a1.x + a2.x + a3.x) * inv;
    r.y = (a0.y + a1.y + a2.y + a3.y) * inv;
    r.z = (a0.z + a1.z + a2.z + a3.z) * inv;
    r.w = (a0.w + a1.w + a2.w + a3.w) * inv;

    reinterpret_cast<float4*>(out)[b * (D_SZ / 4) + tid] = r;
}

extern "C" void kernel_launch(void* const* d_in, const int* in_sizes, int n_in,
                              void* d_out, int out_size) {
    const float* hidden = (const float*)d_in[0];
    const int*   ids    = (const int*)  d_in[1];
    const int*   mask   = (const int*)  d_in[2];
    const float* idf    = (const float*)d_in[3];
    float*       out    = (float*)d_out;

    sbert_idf_pool_kernel<<<B_SZ, THREADS>>>(hidden, ids, mask, idf, out);
}